// round 1
// baseline (speedup 1.0000x reference)
#include <cuda_runtime.h>
#include <math.h>
#include <stdint.h>

// Problem constants
#define BB 2
#define NN 384
#define CS 256
#define CZ 128
#define BN (BB*NN)          // 768
#define PAIRS (BB*NN*NN)    // 294912
#define RELTAB (2*NN - 1)   // 767

// ---------------------------------------------------------------------------
// Scratch (device globals; no allocation allowed)
// ---------------------------------------------------------------------------
__device__ float g_prot[BN * 73];
__device__ float g_nodein[BN * 145];
__device__ float g_A[BN * CZ];      // prot_i @ ew1[0:73] + eb1
__device__ float g_Bm[BN * CZ];     // prot_j @ ew1[73:146]
__device__ float g_Rtab[RELTAB * CZ];
__device__ unsigned char g_dbin[PAIRS];

// ---------------------------------------------------------------------------
// K1: per-residue features -> prot_t_embed (73) and node_in (145)
// ---------------------------------------------------------------------------
__global__ void k_feats(const float* __restrict__ atom10,
                        const int*   __restrict__ seq,
                        const float* __restrict__ t,
                        const float* __restrict__ fmask,
                        const float* __restrict__ trans,
                        const float* __restrict__ rots,
                        const float* __restrict__ atom14)
{
    int bn = blockIdx.x * blockDim.x + threadIdx.x;
    if (bn >= BN) return;
    int b = bn / NN;
    float* prot = g_prot + bn * 73;
    float* ni   = g_nodein + bn * 145;

    // timestep embedding (dim 32)
    const float tv = t[b];
    const float LOG1E4 = 9.210340371976184f;   // ln(10000)
    #pragma unroll
    for (int k = 0; k < 16; k++) {
        float freq = expf(-(float)k * (LOG1E4 / 15.0f));
        float ang  = tv * 10000.0f * freq;
        prot[k]      = sinf(ang);
        prot[16 + k] = cosf(ang);
    }
    prot[32] = fmask[bn];

    // noised_atom10_local (30) + 1/(1+d^2) (10)
    #pragma unroll
    for (int a = 0; a < 10; a++) {
        float x = atom10[bn * 30 + a * 3 + 0];
        float y = atom10[bn * 30 + a * 3 + 1];
        float z = atom10[bn * 30 + a * 3 + 2];
        prot[33 + a * 3 + 0] = x;
        prot[33 + a * 3 + 1] = y;
        prot[33 + a * 3 + 2] = z;
        prot[63 + a] = 1.0f / (1.0f + (x * x + y * y + z * z));
    }

    // node_in[0:73] = prot
    #pragma unroll
    for (int k = 0; k < 73; k++) ni[k] = prot[k];

    // index embedding of seq_idx (32)
    const float LOG2056 = 7.6285219817792950f; // ln(2056)
    const float PI = 3.14159265358979323846f;
    float idx = (float)seq[bn];
    #pragma unroll
    for (int k = 0; k < 16; k++) {
        float denom = expf((float)k * (LOG2056 / 16.0f));
        float ang = idx * PI / denom;
        ni[73 + k] = sinf(ang);
        ni[89 + k] = cosf(ang);
    }

    // local frame atoms: atoms 4..13 of sc_atom14
    const float* R = rots + bn * 9;
    float tr0 = trans[bn * 3 + 0];
    float tr1 = trans[bn * 3 + 1];
    float tr2 = trans[bn * 3 + 2];
    #pragma unroll
    for (int a = 0; a < 10; a++) {
        const float* ap = atom14 + ((size_t)bn * 14 + 4 + a) * 3;
        float p0 = ap[0] - tr0, p1 = ap[1] - tr1, p2 = ap[2] - tr2;
        // l_i = sum_j R[j,i] * p_j   (einsum 'bnji,bnaj->bnai')
        float l0 = R[0] * p0 + R[3] * p1 + R[6] * p2;
        float l1 = R[1] * p0 + R[4] * p1 + R[7] * p2;
        float l2 = R[2] * p0 + R[5] * p1 + R[8] * p2;
        ni[105 + a * 3 + 0] = l0;
        ni[105 + a * 3 + 1] = l1;
        ni[105 + a * 3 + 2] = l2;
        float d = sqrtf(l0 * l0 + l1 * l1 + l2 * l2);
        ni[135 + a] = 1.0f / (1.0f + d);
    }
}

// ---------------------------------------------------------------------------
// K2: node MLP + LN -> out_node   (one block per residue, 256 threads)
// ---------------------------------------------------------------------------
__global__ void k_node_mlp(const float* __restrict__ w1, const float* __restrict__ b1,
                           const float* __restrict__ w2, const float* __restrict__ b2,
                           const float* __restrict__ w3, const float* __restrict__ b3,
                           const float* __restrict__ g,  const float* __restrict__ bt,
                           float* __restrict__ out)
{
    __shared__ float sx[160];
    __shared__ float sh[256];
    __shared__ float sred[32];
    int bn = blockIdx.x;
    int tid = threadIdx.x;

    for (int k = tid; k < 145; k += 256) sx[k] = g_nodein[bn * 145 + k];
    __syncthreads();

    float acc = b1[tid];
    #pragma unroll 5
    for (int k = 0; k < 145; k++) acc += sx[k] * w1[k * 256 + tid];
    acc = fmaxf(acc, 0.0f);
    sh[tid] = acc;
    __syncthreads();

    float acc2 = b2[tid];
    #pragma unroll 8
    for (int k = 0; k < 256; k++) acc2 += sh[k] * w2[k * 256 + tid];
    acc2 = fmaxf(acc2, 0.0f);
    __syncthreads();
    sh[tid] = acc2;
    __syncthreads();

    float v = b3[tid];
    #pragma unroll 8
    for (int k = 0; k < 256; k++) v += sh[k] * w3[k * 256 + tid];

    // block reduction for mean / var
    float s = v, ss = v * v;
    #pragma unroll
    for (int o = 16; o > 0; o >>= 1) {
        s  += __shfl_xor_sync(0xffffffffu, s, o);
        ss += __shfl_xor_sync(0xffffffffu, ss, o);
    }
    int w = tid >> 5, l = tid & 31;
    if (l == 0) { sred[w] = s; sred[8 + w] = ss; }
    __syncthreads();
    if (tid == 0) {
        float S = 0.0f, SS = 0.0f;
        #pragma unroll
        for (int i = 0; i < 8; i++) { S += sred[i]; SS += sred[8 + i]; }
        float mu = S / 256.0f;
        sred[16] = mu;
        sred[17] = rsqrtf(SS / 256.0f - mu * mu + 1e-5f);
    }
    __syncthreads();
    out[(size_t)bn * 256 + tid] = (v - sred[16]) * sred[17] * g[tid] + bt[tid];
}

// ---------------------------------------------------------------------------
// K3: A = prot @ ew1[0:73] + eb1,  Bm = prot @ ew1[73:146]
// ---------------------------------------------------------------------------
__global__ void k_AB(const float* __restrict__ ew1, const float* __restrict__ eb1)
{
    __shared__ float sp[73];
    int bn = blockIdx.x;
    int c  = threadIdx.x;  // 0..127
    if (c < 73) sp[c] = g_prot[bn * 73 + c];
    __syncthreads();
    float a  = eb1[c];
    float bm = 0.0f;
    #pragma unroll
    for (int k = 0; k < 73; k++) {
        float p = sp[k];
        a  += p * ew1[k * CZ + c];
        bm += p * ew1[(73 + k) * CZ + c];
    }
    g_A[bn * CZ + c]  = a;
    g_Bm[bn * CZ + c] = bm;
}

// ---------------------------------------------------------------------------
// K4: Rtab[r] = index_embedding(r-383) @ ew1[146:178]
// ---------------------------------------------------------------------------
__global__ void k_rtab(const float* __restrict__ ew1)
{
    __shared__ float sie[32];
    int r = blockIdx.x;      // 0..766
    int c = threadIdx.x;     // 0..127
    if (c < 32) {
        const float LOG2056 = 7.6285219817792950f;
        const float PI = 3.14159265358979323846f;
        int k = c & 15;
        float denom = expf((float)k * (LOG2056 / 16.0f));
        float ang = (float)(r - (NN - 1)) * PI / denom;
        sie[c] = (c < 16) ? sinf(ang) : cosf(ang);
    }
    __syncthreads();
    float acc = 0.0f;
    #pragma unroll
    for (int k = 0; k < 32; k++) acc += sie[k] * ew1[(146 + k) * CZ + c];
    g_Rtab[r * CZ + c] = acc;
}

// ---------------------------------------------------------------------------
// K5: distogram bin per pair (one-hot -> single row index; 255 = no bin)
// ---------------------------------------------------------------------------
__global__ void k_dbin(const float* __restrict__ trans)
{
    int p = blockIdx.x * blockDim.x + threadIdx.x;
    if (p >= PAIRS) return;
    int b  = p / (NN * NN);
    int ij = p % (NN * NN);
    int i = ij / NN, j = ij % NN;
    float dx = trans[((size_t)b * NN + i) * 3 + 0] - trans[((size_t)b * NN + j) * 3 + 0];
    float dy = trans[((size_t)b * NN + i) * 3 + 1] - trans[((size_t)b * NN + j) * 3 + 1];
    float dz = trans[((size_t)b * NN + i) * 3 + 2] - trans[((size_t)b * NN + j) * 3 + 2];
    float d = sqrtf(dx * dx + dy * dy + dz * dz);
    const float lo0  = 1e-5f;
    const float step = (20.0f - 1e-5f) / 21.0f;
    unsigned char bin = 255;
    #pragma unroll
    for (int k = 0; k < 22; k++) {
        float lower = lo0 + (float)k * step;
        float upper = (k < 21) ? (lo0 + (float)(k + 1) * step) : 1e8f;
        if (d > lower && d < upper) { bin = (unsigned char)k; break; }
    }
    g_dbin[p] = bin;
}

// ---------------------------------------------------------------------------
// Edge main kernel: per (b,i) block, 6 tiles of 64 j's.
// h1 = relu(A_i + Bm_j + Rtab[i-j] + Wd[bin]); two 128x128 fp32 GEMM layers
// with W2/W3 in SMEM; LN; store.
// ---------------------------------------------------------------------------
#define HSTRIDE 129          // padded row stride (bank-conflict-free col access)
#define EDGE_SMEM_FLOATS (16384 + 16384 + 64*HSTRIDE + 64*HSTRIDE + 128 + 64 + 64 + 64 + 64)
#define EDGE_SMEM_BYTES  (EDGE_SMEM_FLOATS * 4)

template <bool RELU>
__device__ __forceinline__ void gemm_tile(const float* __restrict__ sIn,
                                          const float* __restrict__ sW,
                                          const float* __restrict__ bias,
                                          float* __restrict__ sOut, int tid)
{
    const int c0 = (tid & 15) * 8;
    const int r0 = (tid >> 4) * 4;
    float acc[4][8];
    #pragma unroll
    for (int m = 0; m < 4; m++)
        #pragma unroll
        for (int n = 0; n < 8; n++) acc[m][n] = 0.0f;

    const float* a0p = sIn + r0 * HSTRIDE;
    #pragma unroll 4
    for (int k = 0; k < 128; k++) {
        float a0 = a0p[k];
        float a1 = a0p[HSTRIDE + k];
        float a2 = a0p[2 * HSTRIDE + k];
        float a3 = a0p[3 * HSTRIDE + k];
        float4 blo = *(const float4*)(sW + k * 128 + c0);
        float4 bhi = *(const float4*)(sW + k * 128 + c0 + 4);
        float bb[8] = {blo.x, blo.y, blo.z, blo.w, bhi.x, bhi.y, bhi.z, bhi.w};
        #pragma unroll
        for (int n = 0; n < 8; n++) {
            acc[0][n] += a0 * bb[n];
            acc[1][n] += a1 * bb[n];
            acc[2][n] += a2 * bb[n];
            acc[3][n] += a3 * bb[n];
        }
    }
    #pragma unroll
    for (int m = 0; m < 4; m++)
        #pragma unroll
        for (int n = 0; n < 8; n++) {
            float v = acc[m][n] + bias[c0 + n];
            if (RELU) v = fmaxf(v, 0.0f);
            sOut[(r0 + m) * HSTRIDE + c0 + n] = v;
        }
}

__global__ void k_edge(const float* __restrict__ ew1,
                       const float* __restrict__ w2, const float* __restrict__ b2,
                       const float* __restrict__ w3, const float* __restrict__ b3,
                       const float* __restrict__ eg, const float* __restrict__ ebt,
                       const int*   __restrict__ seq,
                       float* __restrict__ out_edge)
{
    extern __shared__ float sm[];
    float* sW2  = sm;                       // 16384
    float* sW3  = sW2 + 16384;              // 16384
    float* sB0  = sW3 + 16384;              // 64*HSTRIDE
    float* sB1  = sB0 + 64 * HSTRIDE;       // 64*HSTRIDE
    float* sAi  = sB1 + 64 * HSTRIDE;       // 128
    float* sMu  = sAi + 128;                // 64
    float* sRs  = sMu + 64;                 // 64
    int*   sRel = (int*)(sRs + 64);         // 64
    int*   sBin = sRel + 64;                // 64

    const int tid = threadIdx.x;
    const int bi  = blockIdx.x;             // 0..767 = b*N + i
    const int b   = bi / NN;
    const int si  = seq[bi];

    for (int e = tid; e < 16384; e += 256) { sW2[e] = w2[e]; sW3[e] = w3[e]; }
    for (int e = tid; e < 128; e += 256)   sAi[e] = g_A[bi * CZ + e];
    __syncthreads();

    for (int jt = 0; jt < 6; jt++) {
        const int j0 = jt * 64;
        if (tid < 64) {
            int j = j0 + tid;
            int rel = si - seq[b * NN + j] + (NN - 1);
            rel = min(max(rel, 0), RELTAB - 1);
            sRel[tid] = rel;
            sBin[tid] = (int)g_dbin[(size_t)bi * NN + j];
        }
        __syncthreads();

        // h1 fill
        for (int e = tid; e < 64 * 128; e += 256) {
            int r = e >> 7, c = e & 127;
            int j = j0 + r;
            float v = sAi[c]
                    + g_Bm[((size_t)b * NN + j) * CZ + c]
                    + g_Rtab[(size_t)sRel[r] * CZ + c];
            int bin = sBin[r];
            if (bin != 255) v += ew1[(178 + bin) * CZ + c];
            sB0[r * HSTRIDE + c] = fmaxf(v, 0.0f);
        }
        __syncthreads();

        gemm_tile<true >(sB0, sW2, b2, sB1, tid);
        __syncthreads();
        gemm_tile<false>(sB1, sW3, b3, sB0, tid);
        __syncthreads();

        // LayerNorm stats per row
        if (tid < 64) {
            const float* row = sB0 + tid * HSTRIDE;
            float s = 0.0f, ss = 0.0f;
            #pragma unroll 8
            for (int c = 0; c < 128; c++) { float v = row[c]; s += v; ss += v * v; }
            float mu = s * (1.0f / 128.0f);
            sMu[tid] = mu;
            sRs[tid] = rsqrtf(ss * (1.0f / 128.0f) - mu * mu + 1e-5f);
        }
        __syncthreads();

        size_t base = (((size_t)bi) * NN + j0) * CZ;
        for (int e = tid; e < 64 * 128; e += 256) {
            int r = e >> 7, c = e & 127;
            out_edge[base + (size_t)r * CZ + c] =
                (sB0[r * HSTRIDE + c] - sMu[r]) * sRs[r] * eg[c] + ebt[c];
        }
        __syncthreads();
    }
}

// ---------------------------------------------------------------------------
// Launch
// ---------------------------------------------------------------------------
extern "C" void kernel_launch(void* const* d_in, const int* in_sizes, int n_in,
                              void* d_out, int out_size)
{
    const float* atom10 = (const float*)d_in[0];
    const int*   seq    = (const int*)  d_in[1];
    const float* t      = (const float*)d_in[2];
    const float* fmask  = (const float*)d_in[3];
    // d_in[4] = node_mask (unused by reference)
    const float* trans  = (const float*)d_in[5];
    const float* rots   = (const float*)d_in[6];
    const float* atom14 = (const float*)d_in[7];
    const float* nw1 = (const float*)d_in[8];
    const float* nb1 = (const float*)d_in[9];
    const float* nw2 = (const float*)d_in[10];
    const float* nb2 = (const float*)d_in[11];
    const float* nw3 = (const float*)d_in[12];
    const float* nb3 = (const float*)d_in[13];
    const float* ng  = (const float*)d_in[14];
    const float* nbt = (const float*)d_in[15];
    const float* ew1 = (const float*)d_in[16];
    const float* eb1 = (const float*)d_in[17];
    const float* ew2 = (const float*)d_in[18];
    const float* eb2 = (const float*)d_in[19];
    const float* ew3 = (const float*)d_in[20];
    const float* eb3 = (const float*)d_in[21];
    const float* eg  = (const float*)d_in[22];
    const float* ebt = (const float*)d_in[23];

    float* out_node = (float*)d_out;                 // [B,N,256]
    float* out_edge = out_node + (size_t)BN * CS;    // [B,N,N,128]

    k_feats<<<3, 256>>>(atom10, seq, t, fmask, trans, rots, atom14);
    k_node_mlp<<<BN, 256>>>(nw1, nb1, nw2, nb2, nw3, nb3, ng, nbt, out_node);
    k_AB<<<BN, 128>>>(ew1, eb1);
    k_rtab<<<RELTAB, 128>>>(ew1);
    k_dbin<<<(PAIRS + 255) / 256, 256>>>(trans);

    cudaFuncSetAttribute(k_edge, cudaFuncAttributeMaxDynamicSharedMemorySize,
                         EDGE_SMEM_BYTES);
    k_edge<<<BN, 256, EDGE_SMEM_BYTES>>>(ew1, ew2, eb2, ew3, eb3, eg, ebt, seq, out_edge);
}

// round 8
// speedup vs baseline: 3.5854x; 3.5854x over previous
#include <cuda_runtime.h>
#include <math.h>
#include <stdint.h>

// Problem constants
#define BB 2
#define NN 384
#define CS 256
#define CZ 128
#define BN (BB*NN)          // 768
#define RELTAB (2*NN - 1)   // 767
#define PADW 132            // padded row stride (floats) for conflict-free frags

// ---------------------------------------------------------------------------
// Scratch (device globals; no allocation allowed)
// ---------------------------------------------------------------------------
__device__ float g_prot[BN * 73];
__device__ float g_nodein[BN * 145];
__device__ float g_A[BN * CZ];      // prot_i @ ew1[0:73] + eb1
__device__ float g_Bm[BN * CZ];     // prot_j @ ew1[73:146]
__device__ float g_Rtab[RELTAB * CZ];
__device__ float g_W2T[CZ * CZ];    // W2T[n][k] = w2[k][n]
__device__ float g_W3T[CZ * CZ];

// ---------------------------------------------------------------------------
// K1: per-residue features -> prot_t_embed (73) and node_in (145)
// ---------------------------------------------------------------------------
__global__ void k_feats(const float* __restrict__ atom10,
                        const int*   __restrict__ seq,
                        const float* __restrict__ t,
                        const float* __restrict__ fmask,
                        const float* __restrict__ trans,
                        const float* __restrict__ rots,
                        const float* __restrict__ atom14)
{
    int bn = blockIdx.x * blockDim.x + threadIdx.x;
    if (bn >= BN) return;
    int b = bn / NN;
    float* prot = g_prot + bn * 73;
    float* ni   = g_nodein + bn * 145;

    const float tv = t[b];
    const float LOG1E4 = 9.210340371976184f;
    #pragma unroll
    for (int k = 0; k < 16; k++) {
        float freq = expf(-(float)k * (LOG1E4 / 15.0f));
        float ang  = tv * 10000.0f * freq;
        prot[k]      = sinf(ang);
        prot[16 + k] = cosf(ang);
    }
    prot[32] = fmask[bn];

    #pragma unroll
    for (int a = 0; a < 10; a++) {
        float x = atom10[bn * 30 + a * 3 + 0];
        float y = atom10[bn * 30 + a * 3 + 1];
        float z = atom10[bn * 30 + a * 3 + 2];
        prot[33 + a * 3 + 0] = x;
        prot[33 + a * 3 + 1] = y;
        prot[33 + a * 3 + 2] = z;
        prot[63 + a] = 1.0f / (1.0f + (x * x + y * y + z * z));
    }

    #pragma unroll
    for (int k = 0; k < 73; k++) ni[k] = prot[k];

    const float LOG2056 = 7.6285219817792950f;
    const float PI = 3.14159265358979323846f;
    float idx = (float)seq[bn];
    #pragma unroll
    for (int k = 0; k < 16; k++) {
        float denom = expf((float)k * (LOG2056 / 16.0f));
        float ang = idx * PI / denom;
        ni[73 + k] = sinf(ang);
        ni[89 + k] = cosf(ang);
    }

    const float* R = rots + bn * 9;
    float tr0 = trans[bn * 3 + 0];
    float tr1 = trans[bn * 3 + 1];
    float tr2 = trans[bn * 3 + 2];
    #pragma unroll
    for (int a = 0; a < 10; a++) {
        const float* ap = atom14 + ((size_t)bn * 14 + 4 + a) * 3;
        float p0 = ap[0] - tr0, p1 = ap[1] - tr1, p2 = ap[2] - tr2;
        float l0 = R[0] * p0 + R[3] * p1 + R[6] * p2;
        float l1 = R[1] * p0 + R[4] * p1 + R[7] * p2;
        float l2 = R[2] * p0 + R[5] * p1 + R[8] * p2;
        ni[105 + a * 3 + 0] = l0;
        ni[105 + a * 3 + 1] = l1;
        ni[105 + a * 3 + 2] = l2;
        float d = sqrtf(l0 * l0 + l1 * l1 + l2 * l2);
        ni[135 + a] = 1.0f / (1.0f + d);
    }
}

// ---------------------------------------------------------------------------
// K2: node MLP + LN -> out_node
// ---------------------------------------------------------------------------
__global__ void k_node_mlp(const float* __restrict__ w1, const float* __restrict__ b1,
                           const float* __restrict__ w2, const float* __restrict__ b2,
                           const float* __restrict__ w3, const float* __restrict__ b3,
                           const float* __restrict__ g,  const float* __restrict__ bt,
                           float* __restrict__ out)
{
    __shared__ float sx[160];
    __shared__ float sh[256];
    __shared__ float sred[32];
    int bn = blockIdx.x;
    int tid = threadIdx.x;

    for (int k = tid; k < 145; k += 256) sx[k] = g_nodein[bn * 145 + k];
    __syncthreads();

    float acc = b1[tid];
    #pragma unroll 5
    for (int k = 0; k < 145; k++) acc += sx[k] * w1[k * 256 + tid];
    acc = fmaxf(acc, 0.0f);
    sh[tid] = acc;
    __syncthreads();

    float acc2 = b2[tid];
    #pragma unroll 8
    for (int k = 0; k < 256; k++) acc2 += sh[k] * w2[k * 256 + tid];
    acc2 = fmaxf(acc2, 0.0f);
    __syncthreads();
    sh[tid] = acc2;
    __syncthreads();

    float v = b3[tid];
    #pragma unroll 8
    for (int k = 0; k < 256; k++) v += sh[k] * w3[k * 256 + tid];

    float s = v, ss = v * v;
    #pragma unroll
    for (int o = 16; o > 0; o >>= 1) {
        s  += __shfl_xor_sync(0xffffffffu, s, o);
        ss += __shfl_xor_sync(0xffffffffu, ss, o);
    }
    int w = tid >> 5, l = tid & 31;
    if (l == 0) { sred[w] = s; sred[8 + w] = ss; }
    __syncthreads();
    if (tid == 0) {
        float S = 0.0f, SS = 0.0f;
        #pragma unroll
        for (int i = 0; i < 8; i++) { S += sred[i]; SS += sred[8 + i]; }
        float mu = S / 256.0f;
        sred[16] = mu;
        sred[17] = rsqrtf(SS / 256.0f - mu * mu + 1e-5f);
    }
    __syncthreads();
    out[(size_t)bn * 256 + tid] = (v - sred[16]) * sred[17] * g[tid] + bt[tid];
}

// ---------------------------------------------------------------------------
// K3: A = prot @ ew1[0:73] + eb1,  Bm = prot @ ew1[73:146]
// ---------------------------------------------------------------------------
__global__ void k_AB(const float* __restrict__ ew1, const float* __restrict__ eb1)
{
    __shared__ float sp[73];
    int bn = blockIdx.x;
    int c  = threadIdx.x;
    if (c < 73) sp[c] = g_prot[bn * 73 + c];
    __syncthreads();
    float a  = eb1[c];
    float bm = 0.0f;
    #pragma unroll
    for (int k = 0; k < 73; k++) {
        float p = sp[k];
        a  += p * ew1[k * CZ + c];
        bm += p * ew1[(73 + k) * CZ + c];
    }
    g_A[bn * CZ + c]  = a;
    g_Bm[bn * CZ + c] = bm;
}

// ---------------------------------------------------------------------------
// K4: Rtab[r] = index_embedding(r-383) @ ew1[146:178]
// ---------------------------------------------------------------------------
__global__ void k_rtab(const float* __restrict__ ew1)
{
    __shared__ float sie[32];
    int r = blockIdx.x;
    int c = threadIdx.x;
    if (c < 32) {
        const float LOG2056 = 7.6285219817792950f;
        const float PI = 3.14159265358979323846f;
        int k = c & 15;
        float denom = expf((float)k * (LOG2056 / 16.0f));
        float ang = (float)(r - (NN - 1)) * PI / denom;
        sie[c] = (c < 16) ? sinf(ang) : cosf(ang);
    }
    __syncthreads();
    float acc = 0.0f;
    #pragma unroll
    for (int k = 0; k < 32; k++) acc += sie[k] * ew1[(146 + k) * CZ + c];
    g_Rtab[r * CZ + c] = acc;
}

// ---------------------------------------------------------------------------
// K5: transpose W2, W3
// ---------------------------------------------------------------------------
__global__ void k_wT(const float* __restrict__ w2, const float* __restrict__ w3)
{
    int idx = blockIdx.x * 256 + threadIdx.x;   // 0..16383
    int n = idx >> 7, k = idx & 127;
    g_W2T[idx] = w2[k * CZ + n];
    g_W3T[idx] = w3[k * CZ + n];
}

// ---------------------------------------------------------------------------
// tf32 helpers (baseline sm_80 PTX — legal at .target sm_103)
// ---------------------------------------------------------------------------
__device__ __forceinline__ float tf32r(float x) {
    uint32_t o;
    asm("cvt.rna.tf32.f32 %0, %1;" : "=r"(o) : "f"(x));
    return __uint_as_float(o);
}

// m16n8k8 tf32 mma: acc += A(16x8,row) * B(8x8,col)
__device__ __forceinline__ void mma_tf32_16n8k8(float acc[4],
                                                uint32_t a0, uint32_t a1,
                                                uint32_t a2, uint32_t a3,
                                                uint32_t b0, uint32_t b1) {
    asm volatile(
        "mma.sync.aligned.m16n8k8.row.col.f32.tf32.tf32.f32 "
        "{%0,%1,%2,%3}, {%4,%5,%6,%7}, {%8,%9}, {%0,%1,%2,%3};"
        : "+f"(acc[0]), "+f"(acc[1]), "+f"(acc[2]), "+f"(acc[3])
        : "r"(a0), "r"(a1), "r"(a2), "r"(a3), "r"(b0), "r"(b1));
}

// Warp-tile GEMM: rows [rb, rb+16) x 128 cols, K=128.
// sIn rows padded PADW; sW is W^T [n][k] padded PADW.
__device__ __forceinline__ void gemm_warp(const float* __restrict__ sIn,
                                          const float* __restrict__ sW,
                                          float acc[16][4], int rb, int g, int tg)
{
    const float* arow  = sIn + (rb + g) * PADW + tg;
    const float* arow8 = arow + 8 * PADW;
    #pragma unroll 4
    for (int s = 0; s < 16; s++) {
        int ko = s * 8;
        uint32_t a0 = __float_as_uint(arow [ko]);
        uint32_t a2 = __float_as_uint(arow [ko + 4]);
        uint32_t a1 = __float_as_uint(arow8[ko]);
        uint32_t a3 = __float_as_uint(arow8[ko + 4]);
        #pragma unroll
        for (int nt = 0; nt < 16; nt++) {
            const float* brow = sW + (nt * 8 + g) * PADW + ko + tg;
            uint32_t b0 = __float_as_uint(brow[0]);
            uint32_t b1 = __float_as_uint(brow[4]);
            mma_tf32_16n8k8(acc[nt], a0, a1, a2, a3, b0, b1);
        }
    }
}

// ---------------------------------------------------------------------------
// Edge kernel: grid=768 (one i per CTA); per jt: 128 j-rows x 128 cols,
// two tf32 mma.sync GEMMs + LayerNorm. Warp-local after initial sync.
// ---------------------------------------------------------------------------
// smem floats: sW2 16896 | sW3 16896 | sH 16896 | misc 640
#define SM_FLOATS (3 * 128 * PADW + 5 * 128)
#define SMEM_BYTES (SM_FLOATS * 4)

__global__ void __launch_bounds__(256, 1)
k_edge_mma(const float* __restrict__ ew1,
           const float* __restrict__ b2, const float* __restrict__ b3,
           const float* __restrict__ eg, const float* __restrict__ ebt,
           const int*   __restrict__ seq, const float* __restrict__ trans,
           float* __restrict__ out_edge)
{
    extern __shared__ float sm[];
    float* sW2 = sm;
    float* sW3 = sm + 128 * PADW;
    float* sH  = sm + 2 * 128 * PADW;
    float* sAi = sm + 3 * 128 * PADW;
    float* sB2 = sAi + 128;
    float* sB3 = sB2 + 128;
    float* sEg = sB3 + 128;
    float* sEbt= sEg + 128;

    const int tid  = threadIdx.x;
    const int wid  = tid >> 5, lane = tid & 31;
    const int g    = lane >> 2, tg = lane & 3;
    const int bi   = blockIdx.x;       // 0..767 = b*N + i
    const int b    = bi / NN;
    const int rb   = wid * 16;         // this warp's 16 rows within the tile

    // Weights -> smem (tf32-rounded), plus per-i vectors
    for (int e = tid; e < 128 * 32; e += 256) {
        int n = e >> 5, k4 = (e & 31) << 2;
        float4 v2 = *(const float4*)&g_W2T[n * CZ + k4];
        float4 v3 = *(const float4*)&g_W3T[n * CZ + k4];
        float* d2 = &sW2[n * PADW + k4];
        d2[0] = tf32r(v2.x); d2[1] = tf32r(v2.y);
        d2[2] = tf32r(v2.z); d2[3] = tf32r(v2.w);
        float* d3 = &sW3[n * PADW + k4];
        d3[0] = tf32r(v3.x); d3[1] = tf32r(v3.y);
        d3[2] = tf32r(v3.z); d3[3] = tf32r(v3.w);
    }
    if (tid < 128) {
        sAi[tid] = g_A[bi * CZ + tid];
        sB2[tid] = b2[tid]; sB3[tid] = b3[tid];
        sEg[tid] = eg[tid]; sEbt[tid] = ebt[tid];
    }
    __syncthreads();   // only CTA-wide barrier in the kernel

    const int si = seq[bi];
    const float tix = trans[bi * 3 + 0];
    const float tiy = trans[bi * 3 + 1];
    const float tiz = trans[bi * 3 + 2];

    // Each lane owns column block [lane*4, lane*4+4) of h1 rows.
    float4 ai4 = *(const float4*)&sAi[lane * 4];

    for (int jt = 0; jt < 3; jt++) {
        const int j0 = jt * 128 + rb;  // global row range for this warp

        // lanes 0..15 compute rel-index and distogram bin for row 'lane'
        int relv = 0, binv = 255;
        if (lane < 16) {
            int j = j0 + lane;
            int rel = si - seq[b * NN + j] + (NN - 1);
            relv = min(max(rel, 0), RELTAB - 1);
            float dx = tix - trans[(b * NN + j) * 3 + 0];
            float dy = tiy - trans[(b * NN + j) * 3 + 1];
            float dz = tiz - trans[(b * NN + j) * 3 + 2];
            float d = sqrtf(dx * dx + dy * dy + dz * dz);
            const float lo0  = 1e-5f;
            const float step = (20.0f - 1e-5f) / 21.0f;
            #pragma unroll
            for (int k = 0; k < 22; k++) {
                float lower = lo0 + (float)k * step;
                float upper = (k < 21) ? (lo0 + (float)(k + 1) * step) : 1e8f;
                if (d > lower && d < upper) { binv = k; break; }
            }
        }

        // Build h1 rows (warp-local): relu(Ai + Bm_j + Rtab + Wd[bin]) -> tf32
        #pragma unroll 4
        for (int r = 0; r < 16; r++) {
            int rl = __shfl_sync(0xffffffffu, relv, r);
            int bn_ = __shfl_sync(0xffffffffu, binv, r);
            int j = j0 + r;
            float4 bm = *(const float4*)&g_Bm[((size_t)(b * NN + j)) * CZ + lane * 4];
            float4 rt = *(const float4*)&g_Rtab[(size_t)rl * CZ + lane * 4];
            float4 v;
            v.x = ai4.x + bm.x + rt.x;
            v.y = ai4.y + bm.y + rt.y;
            v.z = ai4.z + bm.z + rt.z;
            v.w = ai4.w + bm.w + rt.w;
            if (bn_ != 255) {
                float4 wd = *(const float4*)&ew1[(size_t)(178 + bn_) * CZ + lane * 4];
                v.x += wd.x; v.y += wd.y; v.z += wd.z; v.w += wd.w;
            }
            float* dst = &sH[(rb + r) * PADW + lane * 4];
            dst[0] = tf32r(fmaxf(v.x, 0.0f));
            dst[1] = tf32r(fmaxf(v.y, 0.0f));
            dst[2] = tf32r(fmaxf(v.z, 0.0f));
            dst[3] = tf32r(fmaxf(v.w, 0.0f));
        }
        __syncwarp();

        // GEMM1: D1 = h1 @ W2
        float acc[16][4];
        #pragma unroll
        for (int nt = 0; nt < 16; nt++) {
            acc[nt][0] = 0.0f; acc[nt][1] = 0.0f;
            acc[nt][2] = 0.0f; acc[nt][3] = 0.0f;
        }
        gemm_warp(sH, sW2, acc, rb, g, tg);

        // Bounce: relu(D1 + b2) -> sH (tf32), same warp rows
        #pragma unroll
        for (int nt = 0; nt < 16; nt++) {
            int c0 = nt * 8 + 2 * tg;
            float bb0 = sB2[c0], bb1 = sB2[c0 + 1];
            float2 lo, hi;
            lo.x = tf32r(fmaxf(acc[nt][0] + bb0, 0.0f));
            lo.y = tf32r(fmaxf(acc[nt][1] + bb1, 0.0f));
            hi.x = tf32r(fmaxf(acc[nt][2] + bb0, 0.0f));
            hi.y = tf32r(fmaxf(acc[nt][3] + bb1, 0.0f));
            *(float2*)&sH[(rb + g) * PADW + c0]     = lo;
            *(float2*)&sH[(rb + g + 8) * PADW + c0] = hi;
        }
        __syncwarp();

        // GEMM2: D2 = relu(D1+b2) @ W3
        #pragma unroll
        for (int nt = 0; nt < 16; nt++) {
            acc[nt][0] = 0.0f; acc[nt][1] = 0.0f;
            acc[nt][2] = 0.0f; acc[nt][3] = 0.0f;
        }
        gemm_warp(sH, sW3, acc, rb, g, tg);

        // Epilogue: +b3, LayerNorm per row (quad shfl reduce), scale, store
        float sg = 0.0f, qg = 0.0f, sg8 = 0.0f, qg8 = 0.0f;
        #pragma unroll
        for (int nt = 0; nt < 16; nt++) {
            int c0 = nt * 8 + 2 * tg;
            float bb0 = sB3[c0], bb1 = sB3[c0 + 1];
            float v0 = acc[nt][0] + bb0, v1 = acc[nt][1] + bb1;
            float v2 = acc[nt][2] + bb0, v3 = acc[nt][3] + bb1;
            acc[nt][0] = v0; acc[nt][1] = v1; acc[nt][2] = v2; acc[nt][3] = v3;
            sg  += v0 + v1;           qg  += v0 * v0 + v1 * v1;
            sg8 += v2 + v3;           qg8 += v2 * v2 + v3 * v3;
        }
        sg  += __shfl_xor_sync(0xffffffffu, sg, 1);
        sg  += __shfl_xor_sync(0xffffffffu, sg, 2);
        qg  += __shfl_xor_sync(0xffffffffu, qg, 1);
        qg  += __shfl_xor_sync(0xffffffffu, qg, 2);
        sg8 += __shfl_xor_sync(0xffffffffu, sg8, 1);
        sg8 += __shfl_xor_sync(0xffffffffu, sg8, 2);
        qg8 += __shfl_xor_sync(0xffffffffu, qg8, 1);
        qg8 += __shfl_xor_sync(0xffffffffu, qg8, 2);
        float mu  = sg  * (1.0f / 128.0f);
        float rs  = rsqrtf(qg  * (1.0f / 128.0f) - mu  * mu  + 1e-5f);
        float mu8 = sg8 * (1.0f / 128.0f);
        float rs8 = rsqrtf(qg8 * (1.0f / 128.0f) - mu8 * mu8 + 1e-5f);

        float* row0 = out_edge + (((size_t)bi) * NN + j0 + g)     * CZ;
        float* row8 = out_edge + (((size_t)bi) * NN + j0 + g + 8) * CZ;
        #pragma unroll
        for (int nt = 0; nt < 16; nt++) {
            int c0 = nt * 8 + 2 * tg;
            float e0 = sEg[c0],  e1 = sEg[c0 + 1];
            float t0 = sEbt[c0], t1 = sEbt[c0 + 1];
            float2 o0, o8;
            o0.x = (acc[nt][0] - mu)  * rs  * e0 + t0;
            o0.y = (acc[nt][1] - mu)  * rs  * e1 + t1;
            o8.x = (acc[nt][2] - mu8) * rs8 * e0 + t0;
            o8.y = (acc[nt][3] - mu8) * rs8 * e1 + t1;
            *(float2*)&row0[c0] = o0;
            *(float2*)&row8[c0] = o8;
        }
        __syncwarp();   // sH reads done before next jt overwrites
    }
}

// ---------------------------------------------------------------------------
// Launch (6 launches; k_edge_mma is index 5 so ncu -s 5 -c 1 captures it)
// ---------------------------------------------------------------------------
extern "C" void kernel_launch(void* const* d_in, const int* in_sizes, int n_in,
                              void* d_out, int out_size)
{
    const float* atom10 = (const float*)d_in[0];
    const int*   seq    = (const int*)  d_in[1];
    const float* t      = (const float*)d_in[2];
    const float* fmask  = (const float*)d_in[3];
    const float* trans  = (const float*)d_in[5];
    const float* rots   = (const float*)d_in[6];
    const float* atom14 = (const float*)d_in[7];
    const float* nw1 = (const float*)d_in[8];
    const float* nb1 = (const float*)d_in[9];
    const float* nw2 = (const float*)d_in[10];
    const float* nb2 = (const float*)d_in[11];
    const float* nw3 = (const float*)d_in[12];
    const float* nb3 = (const float*)d_in[13];
    const float* ng  = (const float*)d_in[14];
    const float* nbt = (const float*)d_in[15];
    const float* ew1 = (const float*)d_in[16];
    const float* eb1 = (const float*)d_in[17];
    const float* ew2 = (const float*)d_in[18];
    const float* eb2 = (const float*)d_in[19];
    const float* ew3 = (const float*)d_in[20];
    const float* eb3 = (const float*)d_in[21];
    const float* eg  = (const float*)d_in[22];
    const float* ebt = (const float*)d_in[23];

    float* out_node = (float*)d_out;                 // [B,N,256]
    float* out_edge = out_node + (size_t)BN * CS;    // [B,N,N,128]

    k_feats<<<3, 256>>>(atom10, seq, t, fmask, trans, rots, atom14);
    k_node_mlp<<<BN, 256>>>(nw1, nb1, nw2, nb2, nw3, nb3, ng, nbt, out_node);
    k_AB<<<BN, 128>>>(ew1, eb1);
    k_rtab<<<RELTAB, 128>>>(ew1);
    k_wT<<<64, 256>>>(ew2, ew3);

    cudaFuncSetAttribute(k_edge_mma, cudaFuncAttributeMaxDynamicSharedMemorySize,
                         SMEM_BYTES);
    k_edge_mma<<<BN, 256, SMEM_BYTES>>>(ew1, eb2, eb3, eg, ebt, seq, trans,
                                        out_edge);
}

// round 13
// speedup vs baseline: 3.6653x; 1.0223x over previous
#include <cuda_runtime.h>
#include <math.h>
#include <stdint.h>

// Problem constants
#define BB 2
#define NN 384
#define CS 256
#define CZ 128
#define BN (BB*NN)          // 768
#define RELTAB (2*NN - 1)   // 767
#define PADW 132            // padded row stride (floats) for conflict-free frags

// ---------------------------------------------------------------------------
// Scratch (device globals; no allocation allowed)
// ---------------------------------------------------------------------------
__device__ float g_prot[BN * 73];
__device__ float g_nodein[BN * 145];
__device__ float g_A[BN * CZ];      // prot_i @ ew1[0:73] + eb1
__device__ float g_Bm[BN * CZ];     // prot_j @ ew1[73:146]
__device__ float g_Rtab[RELTAB * CZ];
__device__ float g_W2T[CZ * CZ];    // W2T[n][k] = w2[k][n]
__device__ float g_W3T[CZ * CZ];

// ---------------------------------------------------------------------------
// K1: per-residue features -> prot_t_embed (73) and node_in (145)
// ---------------------------------------------------------------------------
__global__ void k_feats(const float* __restrict__ atom10,
                        const int*   __restrict__ seq,
                        const float* __restrict__ t,
                        const float* __restrict__ fmask,
                        const float* __restrict__ trans,
                        const float* __restrict__ rots,
                        const float* __restrict__ atom14)
{
    int bn = blockIdx.x * blockDim.x + threadIdx.x;
    if (bn >= BN) return;
    int b = bn / NN;
    float* prot = g_prot + bn * 73;
    float* ni   = g_nodein + bn * 145;

    const float tv = t[b];
    const float LOG1E4 = 9.210340371976184f;
    #pragma unroll
    for (int k = 0; k < 16; k++) {
        float freq = expf(-(float)k * (LOG1E4 / 15.0f));
        float ang  = tv * 10000.0f * freq;
        prot[k]      = sinf(ang);
        prot[16 + k] = cosf(ang);
    }
    prot[32] = fmask[bn];

    #pragma unroll
    for (int a = 0; a < 10; a++) {
        float x = atom10[bn * 30 + a * 3 + 0];
        float y = atom10[bn * 30 + a * 3 + 1];
        float z = atom10[bn * 30 + a * 3 + 2];
        prot[33 + a * 3 + 0] = x;
        prot[33 + a * 3 + 1] = y;
        prot[33 + a * 3 + 2] = z;
        prot[63 + a] = 1.0f / (1.0f + (x * x + y * y + z * z));
    }

    #pragma unroll
    for (int k = 0; k < 73; k++) ni[k] = prot[k];

    const float LOG2056 = 7.6285219817792950f;
    const float PI = 3.14159265358979323846f;
    float idx = (float)seq[bn];
    #pragma unroll
    for (int k = 0; k < 16; k++) {
        float denom = expf((float)k * (LOG2056 / 16.0f));
        float ang = idx * PI / denom;
        ni[73 + k] = sinf(ang);
        ni[89 + k] = cosf(ang);
    }

    const float* R = rots + bn * 9;
    float tr0 = trans[bn * 3 + 0];
    float tr1 = trans[bn * 3 + 1];
    float tr2 = trans[bn * 3 + 2];
    #pragma unroll
    for (int a = 0; a < 10; a++) {
        const float* ap = atom14 + ((size_t)bn * 14 + 4 + a) * 3;
        float p0 = ap[0] - tr0, p1 = ap[1] - tr1, p2 = ap[2] - tr2;
        float l0 = R[0] * p0 + R[3] * p1 + R[6] * p2;
        float l1 = R[1] * p0 + R[4] * p1 + R[7] * p2;
        float l2 = R[2] * p0 + R[5] * p1 + R[8] * p2;
        ni[105 + a * 3 + 0] = l0;
        ni[105 + a * 3 + 1] = l1;
        ni[105 + a * 3 + 2] = l2;
        float d = sqrtf(l0 * l0 + l1 * l1 + l2 * l2);
        ni[135 + a] = 1.0f / (1.0f + d);
    }
}

// ---------------------------------------------------------------------------
// K_PREP (merged AB + Rtab + W transpose) — keeps edge kernel at launch idx 3
// blocks [0,768): AB; [768,1535): Rtab; [1535,1663): W2T/W3T
// ---------------------------------------------------------------------------
__global__ void k_prep(const float* __restrict__ ew1, const float* __restrict__ eb1,
                       const float* __restrict__ w2,  const float* __restrict__ w3)
{
    __shared__ float sp[73];
    __shared__ float sie[32];
    int blk = blockIdx.x;
    int c = threadIdx.x;    // 0..127

    if (blk < BN) {
        if (c < 73) sp[c] = g_prot[blk * 73 + c];
        __syncthreads();
        float a  = eb1[c];
        float bm = 0.0f;
        #pragma unroll
        for (int k = 0; k < 73; k++) {
            float p = sp[k];
            a  += p * ew1[k * CZ + c];
            bm += p * ew1[(73 + k) * CZ + c];
        }
        g_A[blk * CZ + c]  = a;
        g_Bm[blk * CZ + c] = bm;
    } else if (blk < BN + RELTAB) {
        int r = blk - BN;
        if (c < 32) {
            const float LOG2056 = 7.6285219817792950f;
            const float PI = 3.14159265358979323846f;
            int k = c & 15;
            float denom = expf((float)k * (LOG2056 / 16.0f));
            float ang = (float)(r - (NN - 1)) * PI / denom;
            sie[c] = (c < 16) ? sinf(ang) : cosf(ang);
        }
        __syncthreads();
        float acc = 0.0f;
        #pragma unroll
        for (int k = 0; k < 32; k++) acc += sie[k] * ew1[(146 + k) * CZ + c];
        g_Rtab[r * CZ + c] = acc;
    } else {
        int idx = (blk - BN - RELTAB) * 128 + c;   // 0..16383
        int n = idx >> 7, k = idx & 127;
        g_W2T[idx] = w2[k * CZ + n];
        g_W3T[idx] = w3[k * CZ + n];
    }
}

// ---------------------------------------------------------------------------
// K2: node MLP + LN -> out_node
// ---------------------------------------------------------------------------
__global__ void k_node_mlp(const float* __restrict__ w1, const float* __restrict__ b1,
                           const float* __restrict__ w2, const float* __restrict__ b2,
                           const float* __restrict__ w3, const float* __restrict__ b3,
                           const float* __restrict__ g,  const float* __restrict__ bt,
                           float* __restrict__ out)
{
    __shared__ float sx[160];
    __shared__ float sh[256];
    __shared__ float sred[32];
    int bn = blockIdx.x;
    int tid = threadIdx.x;

    for (int k = tid; k < 145; k += 256) sx[k] = g_nodein[bn * 145 + k];
    __syncthreads();

    float acc = b1[tid];
    #pragma unroll 5
    for (int k = 0; k < 145; k++) acc += sx[k] * w1[k * 256 + tid];
    acc = fmaxf(acc, 0.0f);
    sh[tid] = acc;
    __syncthreads();

    float acc2 = b2[tid];
    #pragma unroll 8
    for (int k = 0; k < 256; k++) acc2 += sh[k] * w2[k * 256 + tid];
    acc2 = fmaxf(acc2, 0.0f);
    __syncthreads();
    sh[tid] = acc2;
    __syncthreads();

    float v = b3[tid];
    #pragma unroll 8
    for (int k = 0; k < 256; k++) v += sh[k] * w3[k * 256 + tid];

    float s = v, ss = v * v;
    #pragma unroll
    for (int o = 16; o > 0; o >>= 1) {
        s  += __shfl_xor_sync(0xffffffffu, s, o);
        ss += __shfl_xor_sync(0xffffffffu, ss, o);
    }
    int w = tid >> 5, l = tid & 31;
    if (l == 0) { sred[w] = s; sred[8 + w] = ss; }
    __syncthreads();
    if (tid == 0) {
        float S = 0.0f, SS = 0.0f;
        #pragma unroll
        for (int i = 0; i < 8; i++) { S += sred[i]; SS += sred[8 + i]; }
        float mu = S / 256.0f;
        sred[16] = mu;
        sred[17] = rsqrtf(SS / 256.0f - mu * mu + 1e-5f);
    }
    __syncthreads();
    out[(size_t)bn * 256 + tid] = (v - sred[16]) * sred[17] * g[tid] + bt[tid];
}

// ---------------------------------------------------------------------------
// tf32 helpers (baseline sm_80 PTX — legal at .target sm_103)
// ---------------------------------------------------------------------------
__device__ __forceinline__ float tf32r(float x) {
    uint32_t o;
    asm("cvt.rna.tf32.f32 %0, %1;" : "=r"(o) : "f"(x));
    return __uint_as_float(o);
}

__device__ __forceinline__ void mma_tf32_16n8k8(float acc[4],
                                                uint32_t a0, uint32_t a1,
                                                uint32_t a2, uint32_t a3,
                                                uint32_t b0, uint32_t b1) {
    asm volatile(
        "mma.sync.aligned.m16n8k8.row.col.f32.tf32.tf32.f32 "
        "{%0,%1,%2,%3}, {%4,%5,%6,%7}, {%8,%9}, {%0,%1,%2,%3};"
        : "+f"(acc[0]), "+f"(acc[1]), "+f"(acc[2]), "+f"(acc[3])
        : "r"(a0), "r"(a1), "r"(a2), "r"(a3), "r"(b0), "r"(b1));
}

// Warp-tile GEMM: 32 rows x 64 cols, K=128. acc[2][8][4].
// B fragments loaded once per (s,nt), reused for both row-frags.
__device__ __forceinline__ void gemm_warp2(const float* __restrict__ sIn,
                                           const float* __restrict__ sW,
                                           float acc[2][8][4],
                                           int rb, int cb, int g, int tg)
{
    const float* a0p = sIn + (rb + g) * PADW + tg;        // rowfrag 0
    const float* a1p = sIn + (rb + 16 + g) * PADW + tg;   // rowfrag 1
    #pragma unroll 4
    for (int s = 0; s < 16; s++) {
        int ko = s * 8;
        uint32_t fa0 = __float_as_uint(a0p[ko]);
        uint32_t fa1 = __float_as_uint(a0p[8 * PADW + ko]);
        uint32_t fa2 = __float_as_uint(a0p[ko + 4]);
        uint32_t fa3 = __float_as_uint(a0p[8 * PADW + ko + 4]);
        uint32_t ga0 = __float_as_uint(a1p[ko]);
        uint32_t ga1 = __float_as_uint(a1p[8 * PADW + ko]);
        uint32_t ga2 = __float_as_uint(a1p[ko + 4]);
        uint32_t ga3 = __float_as_uint(a1p[8 * PADW + ko + 4]);
        #pragma unroll
        for (int nt = 0; nt < 8; nt++) {
            const float* brow = sW + (cb + nt * 8 + g) * PADW + ko + tg;
            uint32_t b0 = __float_as_uint(brow[0]);
            uint32_t b1 = __float_as_uint(brow[4]);
            mma_tf32_16n8k8(acc[0][nt], fa0, fa1, fa2, fa3, b0, b1);
            mma_tf32_16n8k8(acc[1][nt], ga0, ga1, ga2, ga3, b0, b1);
        }
    }
}

// ---------------------------------------------------------------------------
// Edge kernel: grid=768 (one i per CTA), 256 threads (8 warps).
// Warp w: rowgroup rg=w>>1 (32 rows), colgroup cg=w&1 (64 cols).
// Per jt tile (128 j x 128 c): h1 build -> GEMM1 -> bounce -> GEMM2 -> LN.
// ---------------------------------------------------------------------------
// smem floats: sW2 | sW3 | sH (128*PADW each) | misc 640 | sPart 512
#define SM_FLOATS (3 * 128 * PADW + 5 * 128 + 512)
#define SMEM_BYTES (SM_FLOATS * 4)

__global__ void __launch_bounds__(256, 1)
k_edge_mma(const float* __restrict__ ew1,
           const float* __restrict__ b2, const float* __restrict__ b3,
           const float* __restrict__ eg, const float* __restrict__ ebt,
           const int*   __restrict__ seq, const float* __restrict__ trans,
           float* __restrict__ out_edge)
{
    extern __shared__ float sm[];
    float* sW2 = sm;
    float* sW3 = sm + 128 * PADW;
    float* sH  = sm + 2 * 128 * PADW;
    float* sAi = sm + 3 * 128 * PADW;
    float* sB2 = sAi + 128;
    float* sB3 = sB2 + 128;
    float* sEg = sB3 + 128;
    float* sEbt= sEg + 128;
    float* sPart = sEbt + 128;   // [row][cg][{sum,sq}] = row*4 + cg*2 + k

    const int tid  = threadIdx.x;
    const int wid  = tid >> 5, lane = tid & 31;
    const int g    = lane >> 2, tg = lane & 3;
    const int rg   = wid >> 1, cg = wid & 1;
    const int rb   = rg * 32, cb = cg * 64;
    const int hrow = wid * 16;         // h1 build rows for this warp
    const int bi   = blockIdx.x;       // 0..767 = b*N + i
    const int b    = bi / NN;

    // Weights -> smem (tf32-rounded), plus per-i vectors
    for (int e = tid; e < 128 * 32; e += 256) {
        int n = e >> 5, k4 = (e & 31) << 2;
        float4 v2 = *(const float4*)&g_W2T[n * CZ + k4];
        float4 v3 = *(const float4*)&g_W3T[n * CZ + k4];
        float* d2 = &sW2[n * PADW + k4];
        d2[0] = tf32r(v2.x); d2[1] = tf32r(v2.y);
        d2[2] = tf32r(v2.z); d2[3] = tf32r(v2.w);
        float* d3 = &sW3[n * PADW + k4];
        d3[0] = tf32r(v3.x); d3[1] = tf32r(v3.y);
        d3[2] = tf32r(v3.z); d3[3] = tf32r(v3.w);
    }
    if (tid < 128) {
        sAi[tid] = g_A[bi * CZ + tid];
        sB2[tid] = b2[tid]; sB3[tid] = b3[tid];
        sEg[tid] = eg[tid]; sEbt[tid] = ebt[tid];
    }
    __syncthreads();

    const int si = seq[bi];
    const float tix = trans[bi * 3 + 0];
    const float tiy = trans[bi * 3 + 1];
    const float tiz = trans[bi * 3 + 2];
    float4 ai4 = *(const float4*)&sAi[lane * 4];

    for (int jt = 0; jt < 3; jt++) {
        const int jb = jt * 128;          // tile base (global j = jb + tilerow)
        const int j0 = jb + hrow;         // this warp's build rows

        // rel-index / distogram bin for build rows (lanes 0..15)
        int relv = 0, binv = 255;
        if (lane < 16) {
            int j = j0 + lane;
            int rel = si - seq[b * NN + j] + (NN - 1);
            relv = min(max(rel, 0), RELTAB - 1);
            float dx = tix - trans[(b * NN + j) * 3 + 0];
            float dy = tiy - trans[(b * NN + j) * 3 + 1];
            float dz = tiz - trans[(b * NN + j) * 3 + 2];
            float d = sqrtf(dx * dx + dy * dy + dz * dz);
            const float lo0  = 1e-5f;
            const float step = (20.0f - 1e-5f) / 21.0f;
            #pragma unroll
            for (int k = 0; k < 22; k++) {
                float lower = lo0 + (float)k * step;
                float upper = (k < 21) ? (lo0 + (float)(k + 1) * step) : 1e8f;
                if (d > lower && d < upper) { binv = k; break; }
            }
        }

        // Build h1 rows: relu(Ai + Bm_j + Rtab + Wd[bin]) -> tf32
        #pragma unroll 4
        for (int r = 0; r < 16; r++) {
            int rl = __shfl_sync(0xffffffffu, relv, r);
            int bn_ = __shfl_sync(0xffffffffu, binv, r);
            int j = j0 + r;
            float4 bm = *(const float4*)&g_Bm[((size_t)(b * NN + j)) * CZ + lane * 4];
            float4 rt = *(const float4*)&g_Rtab[(size_t)rl * CZ + lane * 4];
            float4 v;
            v.x = ai4.x + bm.x + rt.x;
            v.y = ai4.y + bm.y + rt.y;
            v.z = ai4.z + bm.z + rt.z;
            v.w = ai4.w + bm.w + rt.w;
            if (bn_ != 255) {
                float4 wd = *(const float4*)&ew1[(size_t)(178 + bn_) * CZ + lane * 4];
                v.x += wd.x; v.y += wd.y; v.z += wd.z; v.w += wd.w;
            }
            float* dst = &sH[(hrow + r) * PADW + lane * 4];
            dst[0] = tf32r(fmaxf(v.x, 0.0f));
            dst[1] = tf32r(fmaxf(v.y, 0.0f));
            dst[2] = tf32r(fmaxf(v.z, 0.0f));
            dst[3] = tf32r(fmaxf(v.w, 0.0f));
        }
        __syncthreads();

        // GEMM1: D1 = h1 @ W2
        float acc[2][8][4];
        #pragma unroll
        for (int rf = 0; rf < 2; rf++)
            #pragma unroll
            for (int nt = 0; nt < 8; nt++) {
                acc[rf][nt][0] = 0.0f; acc[rf][nt][1] = 0.0f;
                acc[rf][nt][2] = 0.0f; acc[rf][nt][3] = 0.0f;
            }
        gemm_warp2(sH, sW2, acc, rb, cb, g, tg);
        __syncthreads();

        // Bounce: relu(D1 + b2) -> sH (tf32) in this warp's 32x64 region
        #pragma unroll
        for (int rf = 0; rf < 2; rf++)
            #pragma unroll
            for (int nt = 0; nt < 8; nt++) {
                int c0 = cb + nt * 8 + 2 * tg;
                float bb0 = sB2[c0], bb1 = sB2[c0 + 1];
                float2 lo, hi;
                lo.x = tf32r(fmaxf(acc[rf][nt][0] + bb0, 0.0f));
                lo.y = tf32r(fmaxf(acc[rf][nt][1] + bb1, 0.0f));
                hi.x = tf32r(fmaxf(acc[rf][nt][2] + bb0, 0.0f));
                hi.y = tf32r(fmaxf(acc[rf][nt][3] + bb1, 0.0f));
                int r0 = rb + rf * 16 + g;
                *(float2*)&sH[r0 * PADW + c0]       = lo;
                *(float2*)&sH[(r0 + 8) * PADW + c0] = hi;
            }
        __syncthreads();

        // GEMM2: D2 = relu(D1+b2) @ W3
        #pragma unroll
        for (int rf = 0; rf < 2; rf++)
            #pragma unroll
            for (int nt = 0; nt < 8; nt++) {
                acc[rf][nt][0] = 0.0f; acc[rf][nt][1] = 0.0f;
                acc[rf][nt][2] = 0.0f; acc[rf][nt][3] = 0.0f;
            }
        gemm_warp2(sH, sW3, acc, rb, cb, g, tg);

        // +b3, per-row partials over this warp's 64 cols
        #pragma unroll
        for (int rf = 0; rf < 2; rf++) {
            float sg = 0.0f, qg = 0.0f, sg8 = 0.0f, qg8 = 0.0f;
            #pragma unroll
            for (int nt = 0; nt < 8; nt++) {
                int c0 = cb + nt * 8 + 2 * tg;
                float bb0 = sB3[c0], bb1 = sB3[c0 + 1];
                float v0 = acc[rf][nt][0] + bb0, v1 = acc[rf][nt][1] + bb1;
                float v2 = acc[rf][nt][2] + bb0, v3 = acc[rf][nt][3] + bb1;
                acc[rf][nt][0] = v0; acc[rf][nt][1] = v1;
                acc[rf][nt][2] = v2; acc[rf][nt][3] = v3;
                sg  += v0 + v1;  qg  += v0 * v0 + v1 * v1;
                sg8 += v2 + v3;  qg8 += v2 * v2 + v3 * v3;
            }
            sg  += __shfl_xor_sync(0xffffffffu, sg, 1);
            sg  += __shfl_xor_sync(0xffffffffu, sg, 2);
            qg  += __shfl_xor_sync(0xffffffffu, qg, 1);
            qg  += __shfl_xor_sync(0xffffffffu, qg, 2);
            sg8 += __shfl_xor_sync(0xffffffffu, sg8, 1);
            sg8 += __shfl_xor_sync(0xffffffffu, sg8, 2);
            qg8 += __shfl_xor_sync(0xffffffffu, qg8, 1);
            qg8 += __shfl_xor_sync(0xffffffffu, qg8, 2);
            if (tg == 0) {
                int r0 = rb + rf * 16 + g;
                sPart[r0 * 4 + cg * 2 + 0] = sg;
                sPart[r0 * 4 + cg * 2 + 1] = qg;
                sPart[(r0 + 8) * 4 + cg * 2 + 0] = sg8;
                sPart[(r0 + 8) * 4 + cg * 2 + 1] = qg8;
            }
        }
        __syncthreads();   // partials ready; also: all GEMM2 reads of sH done

        // Final LN + store (warp's 32x64 region)
        #pragma unroll
        for (int rf = 0; rf < 2; rf++) {
            int r0 = rb + rf * 16 + g;
            float s0 = sPart[r0 * 4 + 0] + sPart[r0 * 4 + 2];
            float q0 = sPart[r0 * 4 + 1] + sPart[r0 * 4 + 3];
            float s8 = sPart[(r0 + 8) * 4 + 0] + sPart[(r0 + 8) * 4 + 2];
            float q8 = sPart[(r0 + 8) * 4 + 1] + sPart[(r0 + 8) * 4 + 3];
            float mu0 = s0 * (1.0f / 128.0f);
            float rs0 = rsqrtf(q0 * (1.0f / 128.0f) - mu0 * mu0 + 1e-5f);
            float mu8 = s8 * (1.0f / 128.0f);
            float rs8 = rsqrtf(q8 * (1.0f / 128.0f) - mu8 * mu8 + 1e-5f);
            float* row0 = out_edge + (((size_t)bi) * NN + jb + r0) * CZ;
            float* row8 = out_edge + (((size_t)bi) * NN + jb + r0 + 8) * CZ;
            #pragma unroll
            for (int nt = 0; nt < 8; nt++) {
                int c0 = cb + nt * 8 + 2 * tg;
                float e0 = sEg[c0],  e1 = sEg[c0 + 1];
                float t0 = sEbt[c0], t1 = sEbt[c0 + 1];
                float2 o0, o8;
                o0.x = (acc[rf][nt][0] - mu0) * rs0 * e0 + t0;
                o0.y = (acc[rf][nt][1] - mu0) * rs0 * e1 + t1;
                o8.x = (acc[rf][nt][2] - mu8) * rs8 * e0 + t0;
                o8.y = (acc[rf][nt][3] - mu8) * rs8 * e1 + t1;
                *(float2*)&row0[c0] = o0;
                *(float2*)&row8[c0] = o8;
            }
        }
        __syncthreads();   // sPart reads done before next tile rewrites
    }
}

// ---------------------------------------------------------------------------
// Launch: k_feats(0), k_prep(1), k_node_mlp(2), k_edge_mma(3)
// (harness prepends ~2 launches; ncu -s 5 -c 1 then lands on k_edge_mma)
// ---------------------------------------------------------------------------
extern "C" void kernel_launch(void* const* d_in, const int* in_sizes, int n_in,
                              void* d_out, int out_size)
{
    const float* atom10 = (const float*)d_in[0];
    const int*   seq    = (const int*)  d_in[1];
    const float* t      = (const float*)d_in[2];
    const float* fmask  = (const float*)d_in[3];
    const float* trans  = (const float*)d_in[5];
    const float* rots   = (const float*)d_in[6];
    const float* atom14 = (const float*)d_in[7];
    const float* nw1 = (const float*)d_in[8];
    const float* nb1 = (const float*)d_in[9];
    const float* nw2 = (const float*)d_in[10];
    const float* nb2 = (const float*)d_in[11];
    const float* nw3 = (const float*)d_in[12];
    const float* nb3 = (const float*)d_in[13];
    const float* ng  = (const float*)d_in[14];
    const float* nbt = (const float*)d_in[15];
    const float* ew1 = (const float*)d_in[16];
    const float* eb1 = (const float*)d_in[17];
    const float* ew2 = (const float*)d_in[18];
    const float* eb2 = (const float*)d_in[19];
    const float* ew3 = (const float*)d_in[20];
    const float* eb3 = (const float*)d_in[21];
    const float* eg  = (const float*)d_in[22];
    const float* ebt = (const float*)d_in[23];

    float* out_node = (float*)d_out;                 // [B,N,256]
    float* out_edge = out_node + (size_t)BN * CS;    // [B,N,N,128]

    k_feats<<<3, 256>>>(atom10, seq, t, fmask, trans, rots, atom14);
    k_prep<<<BN + RELTAB + 128, 128>>>(ew1, eb1, ew2, ew3);
    k_node_mlp<<<BN, 256>>>(nw1, nb1, nw2, nb2, nw3, nb3, ng, nbt, out_node);

    cudaFuncSetAttribute(k_edge_mma, cudaFuncAttributeMaxDynamicSharedMemorySize,
                         SMEM_BYTES);
    k_edge_mma<<<BN, 256, SMEM_BYTES>>>(ew1, eb2, eb3, eg, ebt, seq, trans,
                                        out_edge);
}